// round 2
// baseline (speedup 1.0000x reference)
#include <cuda_runtime.h>
#include <math.h>

// ---------------------------------------------------------------------------
// TopKRouter: logits = hidden[16384,2048] @ W[64,2048]^T, softmax, top-2,
// weight renorm, z-loss (per-expert variance of logits), load-balance loss
// (CV of gathered-prob mass per expert).
//
// Output layout (float32, concatenated in reference return order):
//   [0,       32768)   expert_weights [T,2]
//   [32768,   65536)   expert_indices [T,2] (as float)
//   [65536, 1114112)   router_logits  [T,64]
//   [1114112]          router_z_loss
//   [1114113]          load_balancing_loss
// ---------------------------------------------------------------------------

#define T_TOK   16384
#define H_DIM   2048
#define E_DIM   64
#define BM      128
#define BK      16
#define AS_LD   132   // padded leading dim (multiple of 4 for float4 reads)
#define BS_LD   68

#define NBLK    (T_TOK / BM)      // 128 GEMM/epilogue blocks

#define W_OFF   0
#define I_OFF   32768
#define L_OFF   65536
#define Z_OFF   1114112
#define LB_OFF  1114113

// Deterministic reduction scratch: per block, 3 arrays of 64 floats
// (sum logits, sum logits^2, sum gathered probs per expert).
__device__ float g_partials[NBLK * 3 * E_DIM];

// ---------------------------------------------------------------------------
// Kernel 1: fp32 SGEMM, 128x64 block tile, 8x4 thread tile, BK=16,
// register-prefetch single-buffer pipeline. Exact fp32 (FFMA) so top-2
// ordering matches the fp32 reference.
// ---------------------------------------------------------------------------
__global__ __launch_bounds__(256, 1)
void gemm_kernel(const float* __restrict__ A,   // [T_TOK, H_DIM]
                 const float* __restrict__ W,   // [E_DIM, H_DIM]
                 float* __restrict__ logits)    // [T_TOK, E_DIM]
{
    __shared__ float As[BK][AS_LD];
    __shared__ float Bs[BK][BS_LD];

    const int tid  = threadIdx.x;
    const int row0 = blockIdx.x * BM;

    const int tx = tid & 15;        // expert group: experts tx*4 .. tx*4+3
    const int ty = tid >> 4;        // token group: tokens  ty*8 .. ty*8+7

    // Global-load assignments (float4 granularity)
    const int fa0 = tid;            // A float4 index 0..255
    const int fa1 = tid + 256;      // A float4 index 256..511
    const int mA0 = fa0 >> 2, kA0 = (fa0 & 3) * 4;
    const int mA1 = fa1 >> 2, kA1 = (fa1 & 3) * 4;
    const int eB  = tid >> 2, kB  = (tid & 3) * 4;

    const float* Arow0 = A + (size_t)(row0 + mA0) * H_DIM;
    const float* Arow1 = A + (size_t)(row0 + mA1) * H_DIM;
    const float* Brow  = W + (size_t)eB * H_DIM;

    float acc[8][4];
#pragma unroll
    for (int i = 0; i < 8; i++)
#pragma unroll
        for (int j = 0; j < 4; j++) acc[i][j] = 0.0f;

    // Prologue: load k-tile 0 into registers
    float4 pa0 = *(const float4*)(Arow0 + 0 + kA0);
    float4 pa1 = *(const float4*)(Arow1 + 0 + kA1);
    float4 pb  = *(const float4*)(Brow  + 0 + kB);

    for (int kt = 0; kt < H_DIM; kt += BK) {
        // Stage registers -> smem (transposed to [k][m])
        As[kA0 + 0][mA0] = pa0.x; As[kA0 + 1][mA0] = pa0.y;
        As[kA0 + 2][mA0] = pa0.z; As[kA0 + 3][mA0] = pa0.w;
        As[kA1 + 0][mA1] = pa1.x; As[kA1 + 1][mA1] = pa1.y;
        As[kA1 + 2][mA1] = pa1.z; As[kA1 + 3][mA1] = pa1.w;
        Bs[kB  + 0][eB ] = pb.x;  Bs[kB  + 1][eB ] = pb.y;
        Bs[kB  + 2][eB ] = pb.z;  Bs[kB  + 3][eB ] = pb.w;
        __syncthreads();

        // Prefetch next k-tile (overlaps with FFMA block below)
        const int ktn = kt + BK;
        if (ktn < H_DIM) {
            pa0 = *(const float4*)(Arow0 + ktn + kA0);
            pa1 = *(const float4*)(Arow1 + ktn + kA1);
            pb  = *(const float4*)(Brow  + ktn + kB);
        }

#pragma unroll
        for (int k = 0; k < BK; k++) {
            float4 a0 = *(const float4*)&As[k][ty * 8];
            float4 a1 = *(const float4*)&As[k][ty * 8 + 4];
            float4 b  = *(const float4*)&Bs[k][tx * 4];
            float av[8] = {a0.x, a0.y, a0.z, a0.w, a1.x, a1.y, a1.z, a1.w};
            float bv[4] = {b.x, b.y, b.z, b.w};
#pragma unroll
            for (int i = 0; i < 8; i++)
#pragma unroll
                for (int j = 0; j < 4; j++)
                    acc[i][j] = fmaf(av[i], bv[j], acc[i][j]);
        }
        __syncthreads();
    }

    // Epilogue: write logits (coalesced float4 per thread-row)
#pragma unroll
    for (int i = 0; i < 8; i++) {
        const int row = row0 + ty * 8 + i;
        float4 v = make_float4(acc[i][0], acc[i][1], acc[i][2], acc[i][3]);
        *(float4*)&logits[(size_t)row * E_DIM + tx * 4] = v;
    }
}

// ---------------------------------------------------------------------------
// Kernel 2: per-token softmax / top-2 / weight renorm + per-block partial
// reductions (deterministic: per-warp register+smem accumulation, fixed-order
// block combine; no float atomics).
// Block = 256 threads = 8 warps; warp w handles 16 consecutive tokens.
// Lane l owns experts l and l+32.
// ---------------------------------------------------------------------------
__global__ __launch_bounds__(256, 1)
void epilogue_kernel(const float* __restrict__ logits,
                     float* __restrict__ out_w,
                     float* __restrict__ out_i)
{
    __shared__ float S1s[8][E_DIM];
    __shared__ float S2s[8][E_DIM];
    __shared__ float Cs[8][E_DIM];

    const int tid = threadIdx.x;
    const int w   = tid >> 5;
    const int l   = tid & 31;
    const unsigned FULL = 0xffffffffu;

    Cs[w][l] = 0.0f; Cs[w][l + 32] = 0.0f;

    float s1a = 0.0f, s1b = 0.0f, s2a = 0.0f, s2b = 0.0f;
    const int tbase = blockIdx.x * 128 + w * 16;

    for (int j = 0; j < 16; j++) {
        const int t = tbase + j;
        const float L0 = logits[(size_t)t * E_DIM + l];
        const float L1 = logits[(size_t)t * E_DIM + 32 + l];

        // warp max over 64 logits
        float m = fmaxf(L0, L1);
#pragma unroll
        for (int o = 16; o > 0; o >>= 1)
            m = fmaxf(m, __shfl_xor_sync(FULL, m, o));

        // sumexp
        float se = expf(L0 - m) + expf(L1 - m);
#pragma unroll
        for (int o = 16; o > 0; o >>= 1)
            se += __shfl_xor_sync(FULL, se, o);

        // --- top-1 (ties -> lower index, matching jax.lax.top_k) ---
        float v1 = L0; int i1 = l;
        if (L1 > L0) { v1 = L1; i1 = l + 32; }
#pragma unroll
        for (int o = 16; o > 0; o >>= 1) {
            float vo = __shfl_xor_sync(FULL, v1, o);
            int   io = __shfl_xor_sync(FULL, i1, o);
            if (vo > v1 || (vo == v1 && io < i1)) { v1 = vo; i1 = io; }
        }
        // --- top-2: mask winner, argmax again ---
        float m0 = (l        == i1) ? -INFINITY : L0;
        float m1 = (l + 32   == i1) ? -INFINITY : L1;
        float v2 = m0; int i2 = l;
        if (m1 > m0) { v2 = m1; i2 = l + 32; }
#pragma unroll
        for (int o = 16; o > 0; o >>= 1) {
            float vo = __shfl_xor_sync(FULL, v2, o);
            int   io = __shfl_xor_sync(FULL, i2, o);
            if (vo > v2 || (vo == v2 && io < i2)) { v2 = vo; i2 = io; }
        }

        const float p1 = expf(v1 - m) / se;
        const float p2 = expf(v2 - m) / se;

        if (l == 0) {
            const float inv = 1.0f / (p1 + p2);
            out_w[(size_t)t * 2 + 0] = p1 * inv;
            out_w[(size_t)t * 2 + 1] = p2 * inv;
            out_i[(size_t)t * 2 + 0] = (float)i1;
            out_i[(size_t)t * 2 + 1] = (float)i2;
            // per-warp gathered-prob accumulation (own smem slice -> no race,
            // fixed token order -> deterministic)
            Cs[w][i1] += p1;
            Cs[w][i2] += p2;
        }

        s1a += L0; s2a = fmaf(L0, L0, s2a);
        s1b += L1; s2b = fmaf(L1, L1, s2b);
    }

    S1s[w][l] = s1a; S1s[w][l + 32] = s1b;
    S2s[w][l] = s2a; S2s[w][l + 32] = s2b;
    __syncthreads();

    // Fixed-order combine of the 8 warps, write block partials
    if (tid < E_DIM) {
        float s1 = 0.0f, s2 = 0.0f, c = 0.0f;
#pragma unroll
        for (int ww = 0; ww < 8; ww++) {
            s1 += S1s[ww][tid];
            s2 += S2s[ww][tid];
            c  += Cs[ww][tid];
        }
        const int b = blockIdx.x;
        g_partials[(b * 3 + 0) * E_DIM + tid] = s1;
        g_partials[(b * 3 + 1) * E_DIM + tid] = s2;
        g_partials[(b * 3 + 2) * E_DIM + tid] = c;
    }
}

// ---------------------------------------------------------------------------
// Kernel 3: fixed-order final reduction + scalar losses.
// ---------------------------------------------------------------------------
__global__ __launch_bounds__(64, 1)
void finalize_kernel(float* __restrict__ out)
{
    __shared__ float sv[E_DIM];
    __shared__ float sf[E_DIM];

    const int e = threadIdx.x;
    float s1 = 0.0f, s2 = 0.0f, c = 0.0f;
    for (int b = 0; b < NBLK; b++) {
        s1 += g_partials[(b * 3 + 0) * E_DIM + e];
        s2 += g_partials[(b * 3 + 1) * E_DIM + e];
        c  += g_partials[(b * 3 + 2) * E_DIM + e];
    }
    const float invT = 1.0f / (float)T_TOK;
    const float mean = s1 * invT;
    sv[e] = s2 * invT - mean * mean;   // per-expert variance
    sf[e] = c * invT;                  // expert_fraction
    __syncthreads();

    if (e == 0) {
        float vsum = 0.0f, fsum = 0.0f;
        for (int i = 0; i < E_DIM; i++) { vsum += sv[i]; fsum += sf[i]; }
        out[Z_OFF] = (vsum / (float)E_DIM) * 0.001f;

        const float meanf = fsum / (float)E_DIM;
        float acc = 0.0f;
        for (int i = 0; i < E_DIM; i++) {
            const float d = sf[i] - meanf;
            acc = fmaf(d, d, acc);
        }
        const float stdv = sqrtf(acc / (float)(E_DIM - 1));  // ddof=1
        out[LB_OFF] = (stdv / (meanf + 1e-8f)) * 0.01f;
    }
}

// ---------------------------------------------------------------------------
extern "C" void kernel_launch(void* const* d_in, const int* in_sizes, int n_in,
                              void* d_out, int out_size)
{
    const float* hs = (const float*)d_in[0];
    const float* W  = (const float*)d_in[1];
    if (n_in >= 2 && in_sizes[0] < in_sizes[1]) {  // defensive input-order guard
        const float* t = hs; hs = W; W = t;
    }

    float* out    = (float*)d_out;
    float* out_w  = out + W_OFF;
    float* out_i  = out + I_OFF;
    float* logits = out + L_OFF;

    gemm_kernel<<<NBLK, 256>>>(hs, W, logits);
    epilogue_kernel<<<NBLK, 256>>>(logits, out_w, out_i);
    finalize_kernel<<<1, 64>>>(out);
}

// round 4
// speedup vs baseline: 1.5328x; 1.5328x over previous
#include <cuda_runtime.h>
#include <math.h>
#include <stdint.h>

#define T_TOK   16384
#define H_DIM   2048
#define E_DIM   64
#define BM      128
#define KC      32
#define NSTG    (H_DIM / KC)          // 64
#define NBLK    (T_TOK / BM)          // 128

#define W_OFF   0
#define I_OFF   32768
#define L_OFF   65536
#define Z_OFF   1114112
#define LB_OFF  1114113

#define PITCH   80                    // bytes per k-row (64B data + 16B pad)
#define ATILE   (BM * PITCH)          // 10240 B per A limb
#define BTILE   (E_DIM * PITCH)       // 5120 B per B limb
#define STG_B   (3 * ATILE + 3 * BTILE) // 46080 B per stage
#define DYN_B   (2 * STG_B)           // 92160

__device__ float g_partials[NBLK * 3 * E_DIM];

__device__ __forceinline__ uint32_t smem_u32(const void* p) {
    uint32_t a;
    asm("{ .reg .u64 t; cvta.to.shared.u64 t, %1; cvt.u32.u64 %0, t; }" : "=r"(a) : "l"(p));
    return a;
}
__device__ __forceinline__ void sts64(uint32_t a, uint32_t x, uint32_t y) {
    asm volatile("st.shared.v2.b32 [%0], {%1, %2};" :: "r"(a), "r"(x), "r"(y));
}
#define LDSM_X4(r0, r1, r2, r3, addr)                                         \
    asm volatile("ldmatrix.sync.aligned.m8n8.x4.shared.b16 {%0,%1,%2,%3}, [%4];" \
                 : "=r"(r0), "=r"(r1), "=r"(r2), "=r"(r3) : "r"(addr))
#define MMA16816(d, a, b)                                                     \
    asm volatile("mma.sync.aligned.m16n8k16.row.col.f32.bf16.bf16.f32 "       \
                 "{%0,%1,%2,%3}, {%4,%5,%6,%7}, {%8,%9}, {%0,%1,%2,%3};"      \
                 : "+f"((d)[0]), "+f"((d)[1]), "+f"((d)[2]), "+f"((d)[3])     \
                 : "r"((a)[0]), "r"((a)[1]), "r"((a)[2]), "r"((a)[3]),        \
                   "r"((b)[0]), "r"((b)[1]))

// 3-limb bf16 split of (x0,x1); each result reg packs (x0 -> low, x1 -> high).
__device__ __forceinline__ void split3(float x0, float x1,
                                       uint32_t& h, uint32_t& m, uint32_t& lo) {
    asm("cvt.rn.bf16x2.f32 %0, %1, %2;" : "=r"(h) : "f"(x1), "f"(x0));
    float r0 = x0 - __uint_as_float(h << 16);
    float r1 = x1 - __uint_as_float(h & 0xffff0000u);
    asm("cvt.rn.bf16x2.f32 %0, %1, %2;" : "=r"(m) : "f"(r1), "f"(r0));
    float s0 = r0 - __uint_as_float(m << 16);
    float s1 = r1 - __uint_as_float(m & 0xffff0000u);
    asm("cvt.rn.bf16x2.f32 %0, %1, %2;" : "=r"(lo) : "f"(s1), "f"(s0));
}

__global__ __launch_bounds__(256, 1)
void fused_router_kernel(const float* __restrict__ A, const float* __restrict__ W,
                         float* __restrict__ out)
{
    extern __shared__ __align__(16) unsigned char dynsm[];
    const uint32_t sbase = smem_u32(dynsm);

    const int tid  = threadIdx.x;
    const int wid  = tid >> 5;
    const int lane = tid & 31;
    const int row0 = blockIdx.x * BM;

    // ---- global-load assignments ----
    // A stage tile: 128 rows x 32 floats = 1024 float4 -> 4 per thread.
    // B stage tile:  64 rows x 32 floats =  512 float4 -> 2 per thread.
    int arow[4], ac4[4], brow[2], bc4[2];
#pragma unroll
    for (int j = 0; j < 4; j++) { int f = tid + j * 256; arow[j] = f >> 3; ac4[j] = f & 7; }
#pragma unroll
    for (int j = 0; j < 2; j++) { int f = tid + j * 256; brow[j] = f >> 3; bc4[j] = f & 7; }

    float4 va[4], vb[2];

    // prologue: stage 0
#pragma unroll
    for (int j = 0; j < 4; j++)
        va[j] = *(const float4*)(A + (size_t)(row0 + arow[j]) * H_DIM + ac4[j] * 4);
#pragma unroll
    for (int j = 0; j < 2; j++)
        vb[j] = *(const float4*)(W + (size_t)brow[j] * H_DIM + bc4[j] * 4);

    {   // split + store stage 0 into buffer 0
        const uint32_t sa = sbase;
#pragma unroll
        for (int j = 0; j < 4; j++) {
            uint32_t h0, m0, l0, h1, m1, l1;
            split3(va[j].x, va[j].y, h0, m0, l0);
            split3(va[j].z, va[j].w, h1, m1, l1);
            uint32_t off = (uint32_t)(arow[j] * PITCH + ac4[j] * 8);
            sts64(sa + off, h0, h1);
            sts64(sa + ATILE + off, m0, m1);
            sts64(sa + 2 * ATILE + off, l0, l1);
        }
        const uint32_t sb = sbase + 3 * ATILE;
#pragma unroll
        for (int j = 0; j < 2; j++) {
            uint32_t h0, m0, l0, h1, m1, l1;
            split3(vb[j].x, vb[j].y, h0, m0, l0);
            split3(vb[j].z, vb[j].w, h1, m1, l1);
            uint32_t off = (uint32_t)(brow[j] * PITCH + bc4[j] * 8);
            sts64(sb + off, h0, h1);
            sts64(sb + BTILE + off, m0, m1);
            sts64(sb + 2 * BTILE + off, l0, l1);
        }
    }
    __syncthreads();

    // ---- ldmatrix per-lane address components ----
    const uint32_t a_off = (uint32_t)((wid * 16 + (lane & 15)) * PITCH + (lane >> 4) * 16);
    const uint32_t b_off = (uint32_t)((((lane & 7) + ((lane >> 4) & 1) * 8)) * PITCH
                                      + ((lane >> 3) & 1) * 16);

    float acc[32];
#pragma unroll
    for (int i = 0; i < 32; i++) acc[i] = 0.0f;

    const int la[6] = {0, 0, 1, 0, 1, 2};   // {hh, hm, mh, hl, mm, lh}
    const int lb[6] = {0, 1, 0, 2, 1, 0};

    for (int i = 0; i < NSTG; i++) {
        // prefetch next stage's fp32 into registers
        if (i + 1 < NSTG) {
            const int kt = (i + 1) * KC;
#pragma unroll
            for (int j = 0; j < 4; j++)
                va[j] = *(const float4*)(A + (size_t)(row0 + arow[j]) * H_DIM + kt + ac4[j] * 4);
#pragma unroll
            for (int j = 0; j < 2; j++)
                vb[j] = *(const float4*)(W + (size_t)brow[j] * H_DIM + kt + bc4[j] * 4);
        }

        // compute on current buffer
        const uint32_t sa = sbase + (uint32_t)(i & 1) * STG_B;
        const uint32_t sb = sa + 3 * ATILE;
#pragma unroll
        for (int ks = 0; ks < 2; ks++) {
            uint32_t aF[3][4], bF[3][16];
#pragma unroll
            for (int L = 0; L < 3; L++)
                LDSM_X4(aF[L][0], aF[L][1], aF[L][2], aF[L][3],
                        sa + L * ATILE + a_off + ks * 32);
#pragma unroll
            for (int L = 0; L < 3; L++)
#pragma unroll
                for (int np = 0; np < 4; np++)
                    LDSM_X4(bF[L][np * 4 + 0], bF[L][np * 4 + 1],
                            bF[L][np * 4 + 2], bF[L][np * 4 + 3],
                            sb + L * BTILE + (uint32_t)(np * 16 * PITCH) + b_off + ks * 32);
#pragma unroll
            for (int t = 0; t < 6; t++)
#pragma unroll
                for (int nt = 0; nt < 8; nt++)
                    MMA16816(acc + nt * 4, aF[la[t]], bF[lb[t]] + nt * 2);
        }

        // split next stage + store into other buffer
        if (i + 1 < NSTG) {
            const uint32_t da = sbase + (uint32_t)((i + 1) & 1) * STG_B;
            const uint32_t db = da + 3 * ATILE;
            uint32_t hh[4][3][2];   // [f4][limb][pair]
#pragma unroll
            for (int j = 0; j < 4; j++) {
                split3(va[j].x, va[j].y, hh[j][0][0], hh[j][1][0], hh[j][2][0]);
                split3(va[j].z, va[j].w, hh[j][0][1], hh[j][1][1], hh[j][2][1]);
            }
            uint32_t bb[2][3][2];
#pragma unroll
            for (int j = 0; j < 2; j++) {
                split3(vb[j].x, vb[j].y, bb[j][0][0], bb[j][1][0], bb[j][2][0]);
                split3(vb[j].z, vb[j].w, bb[j][0][1], bb[j][1][1], bb[j][2][1]);
            }
            __syncthreads();   // everyone done reading the buffer we're about to write
#pragma unroll
            for (int j = 0; j < 4; j++) {
                uint32_t off = (uint32_t)(arow[j] * PITCH + ac4[j] * 8);
                sts64(da + off, hh[j][0][0], hh[j][0][1]);
                sts64(da + ATILE + off, hh[j][1][0], hh[j][1][1]);
                sts64(da + 2 * ATILE + off, hh[j][2][0], hh[j][2][1]);
            }
#pragma unroll
            for (int j = 0; j < 2; j++) {
                uint32_t off = (uint32_t)(brow[j] * PITCH + bc4[j] * 8);
                sts64(db + off, bb[j][0][0], bb[j][0][1]);
                sts64(db + BTILE + off, bb[j][1][0], bb[j][1][1]);
                sts64(db + 2 * BTILE + off, bb[j][2][0], bb[j][2][1]);
            }
            __syncthreads();
        }
    }

    __syncthreads();

    // ---- fused epilogue ----
    float* fsm = (float*)dynsm;                 // [128][68] logits
    int*   si1 = (int*)(fsm + 128 * 68);
    float* sp1 = (float*)(si1 + 128);
    int*   si2 = (int*)(sp1 + 128);
    float* sp2 = (float*)(si2 + 128);

    {   // accumulators -> smem logits tile
        const int mrow = wid * 16 + (lane >> 2);
        const int ncol = (lane & 3) * 2;
#pragma unroll
        for (int nt = 0; nt < 8; nt++) {
            *(float2*)&fsm[mrow * 68 + nt * 8 + ncol] =
                make_float2(acc[nt * 4 + 0], acc[nt * 4 + 1]);
            *(float2*)&fsm[(mrow + 8) * 68 + nt * 8 + ncol] =
                make_float2(acc[nt * 4 + 2], acc[nt * 4 + 3]);
        }
    }
    __syncthreads();

    if (tid < 128) {   // per-token softmax / top-2 / renorm
        float lg[64];
#pragma unroll
        for (int c = 0; c < 64; c++) lg[c] = fsm[tid * 68 + c];

        float mx = lg[0];
#pragma unroll
        for (int c = 1; c < 64; c++) mx = fmaxf(mx, lg[c]);
        float se = 0.0f;
#pragma unroll
        for (int c = 0; c < 64; c++) se += expf(lg[c] - mx);
        float v1 = -INFINITY; int i1 = 0;
#pragma unroll
        for (int c = 0; c < 64; c++)
            if (lg[c] > v1) { v1 = lg[c]; i1 = c; }
        float v2 = -INFINITY; int i2 = 0;
#pragma unroll
        for (int c = 0; c < 64; c++)
            if (c != i1 && lg[c] > v2) { v2 = lg[c]; i2 = c; }

        const float p1 = expf(v1 - mx) / se;
        const float p2 = expf(v2 - mx) / se;
        const float inv = 1.0f / (p1 + p2);
        const int t = row0 + tid;
        out[W_OFF + (size_t)t * 2 + 0] = p1 * inv;
        out[W_OFF + (size_t)t * 2 + 1] = p2 * inv;
        out[I_OFF + (size_t)t * 2 + 0] = (float)i1;
        out[I_OFF + (size_t)t * 2 + 1] = (float)i2;
        si1[tid] = i1; sp1[tid] = p1;
        si2[tid] = i2; sp2[tid] = p2;
    }
    __syncthreads();

    // coalesced logits store (float4 from smem)
#pragma unroll
    for (int j = 0; j < 8; j++) {
        int u = j * 256 + tid, r = u >> 4, c4 = (u & 15) * 4;
        float4 v = *(float4*)&fsm[r * 68 + c4];
        *(float4*)&out[L_OFF + (size_t)(row0 + r) * 64 + c4] = v;
    }

    if (tid < E_DIM) {   // deterministic per-block partials
        float s1 = 0.0f, s2 = 0.0f, cc = 0.0f;
        for (int r = 0; r < 128; r++) {
            float v = fsm[r * 68 + tid];
            s1 += v;
            s2 = fmaf(v, v, s2);
            if (si1[r] == tid) cc += sp1[r];
            if (si2[r] == tid) cc += sp2[r];
        }
        const int b = blockIdx.x;
        g_partials[(b * 3 + 0) * E_DIM + tid] = s1;
        g_partials[(b * 3 + 1) * E_DIM + tid] = s2;
        g_partials[(b * 3 + 2) * E_DIM + tid] = cc;
    }
}

__global__ __launch_bounds__(64, 1)
void finalize_kernel(float* __restrict__ out)
{
    __shared__ float sv[E_DIM], sf[E_DIM];
    const int e = threadIdx.x;
    float s1 = 0.0f, s2 = 0.0f, c = 0.0f;
    for (int b = 0; b < NBLK; b++) {
        s1 += g_partials[(b * 3 + 0) * E_DIM + e];
        s2 += g_partials[(b * 3 + 1) * E_DIM + e];
        c  += g_partials[(b * 3 + 2) * E_DIM + e];
    }
    const float invT = 1.0f / (float)T_TOK;
    const float mean = s1 * invT;
    sv[e] = s2 * invT - mean * mean;
    sf[e] = c * invT;
    __syncthreads();
    if (e == 0) {
        float vsum = 0.0f, fsum = 0.0f;
        for (int i = 0; i < E_DIM; i++) { vsum += sv[i]; fsum += sf[i]; }
        out[Z_OFF] = (vsum / (float)E_DIM) * 0.001f;
        const float meanf = fsum / (float)E_DIM;
        float acc = 0.0f;
        for (int i = 0; i < E_DIM; i++) {
            const float d = sf[i] - meanf;
            acc = fmaf(d, d, acc);
        }
        out[LB_OFF] = (sqrtf(acc / (float)(E_DIM - 1)) / (meanf + 1e-8f)) * 0.01f;
    }
}

extern "C" void kernel_launch(void* const* d_in, const int* in_sizes, int n_in,
                              void* d_out, int out_size)
{
    const float* hs = (const float*)d_in[0];
    const float* W  = (const float*)d_in[1];
    if (n_in >= 2 && in_sizes[0] < in_sizes[1]) {
        const float* t = hs; hs = W; W = t;
    }
    float* out = (float*)d_out;
    cudaFuncSetAttribute(fused_router_kernel,
                         cudaFuncAttributeMaxDynamicSharedMemorySize, DYN_B);
    fused_router_kernel<<<NBLK, 256, DYN_B>>>(hs, W, out);
    finalize_kernel<<<1, 64>>>(out);
}

// round 5
// speedup vs baseline: 2.1439x; 1.3987x over previous
#include <cuda_runtime.h>
#include <cuda_fp16.h>
#include <math.h>
#include <stdint.h>

#define T_TOK   16384
#define H_DIM   2048
#define E_DIM   64
#define BM      128
#define KC      32
#define NSTG    (H_DIM / KC)            // 64
#define NBLK    (T_TOK / BM)            // 128

#define W_OFF   0
#define I_OFF   32768
#define L_OFF   65536
#define Z_OFF   1114112
#define LB_OFF  1114113

#define PITCH   80                      // 64B (32 fp16) + 16B pad per k-row
#define ATILE   (BM * PITCH)            // 10240 B per A limb
#define BTILE   (E_DIM * PITCH)         // 5120 B per B limb
#define STG_B   (2 * ATILE + 2 * BTILE) // 30720 B per stage
#define DYN_B   (2 * STG_B)             // 61440

__device__ float g_partials[NBLK * 3 * E_DIM];
__device__ int   g_done = 0;            // inter-block counter; reset by last block

__device__ __forceinline__ uint32_t smem_u32(const void* p) {
    uint32_t a;
    asm("{ .reg .u64 t; cvta.to.shared.u64 t, %1; cvt.u32.u64 %0, t; }" : "=r"(a) : "l"(p));
    return a;
}
__device__ __forceinline__ void sts64(uint32_t a, uint32_t x, uint32_t y) {
    asm volatile("st.shared.v2.b32 [%0], {%1, %2};" :: "r"(a), "r"(x), "r"(y));
}
#define LDSM_X4(r0, r1, r2, r3, addr)                                         \
    asm volatile("ldmatrix.sync.aligned.m8n8.x4.shared.b16 {%0,%1,%2,%3}, [%4];" \
                 : "=r"(r0), "=r"(r1), "=r"(r2), "=r"(r3) : "r"(addr))
#define MMA16816(d, a, b)                                                     \
    asm volatile("mma.sync.aligned.m16n8k16.row.col.f32.f16.f16.f32 "         \
                 "{%0,%1,%2,%3}, {%4,%5,%6,%7}, {%8,%9}, {%0,%1,%2,%3};"      \
                 : "+f"((d)[0]), "+f"((d)[1]), "+f"((d)[2]), "+f"((d)[3])     \
                 : "r"((a)[0]), "r"((a)[1]), "r"((a)[2]), "r"((a)[3]),        \
                   "r"((b)[0]), "r"((b)[1]))

// 2-limb fp16 split of (x0,x1): h+m represents x to ~2^-22 relative.
// Packed f16x2, x0 in low half. Residual subtraction is fp32-exact (Sterbenz).
__device__ __forceinline__ void split2(float x0, float x1, uint32_t& h, uint32_t& m) {
    __half2 h2 = __floats2half2_rn(x0, x1);
    h = *reinterpret_cast<uint32_t*>(&h2);
    float2 hf = __half22float2(h2);
    __half2 m2 = __floats2half2_rn(x0 - hf.x, x1 - hf.y);
    m = *reinterpret_cast<uint32_t*>(&m2);
}

__global__ __launch_bounds__(256, 1)
void fused_router_kernel(const float* __restrict__ A, const float* __restrict__ W,
                         float* __restrict__ out)
{
    extern __shared__ __align__(16) unsigned char dynsm[];
    const uint32_t sbase = smem_u32(dynsm);

    const int tid  = threadIdx.x;
    const int wid  = tid >> 5;
    const int lane = tid & 31;
    const int row0 = blockIdx.x * BM;

    // global-load assignment: A 1024 float4 -> 4/thread, B 512 float4 -> 2/thread
    int arow[4], ac4[4], brow[2], bc4[2];
#pragma unroll
    for (int j = 0; j < 4; j++) { int f = tid + j * 256; arow[j] = f >> 3; ac4[j] = f & 7; }
#pragma unroll
    for (int j = 0; j < 2; j++) { int f = tid + j * 256; brow[j] = f >> 3; bc4[j] = f & 7; }

    float4 va[4], vb[2];

    // ---- prologue: stage 0 -> buf0 ----
#pragma unroll
    for (int j = 0; j < 4; j++)
        va[j] = *(const float4*)(A + (size_t)(row0 + arow[j]) * H_DIM + ac4[j] * 4);
#pragma unroll
    for (int j = 0; j < 2; j++)
        vb[j] = *(const float4*)(W + (size_t)brow[j] * H_DIM + bc4[j] * 4);
    {
        const uint32_t da = sbase, db = sbase + 2 * ATILE;
#pragma unroll
        for (int j = 0; j < 4; j++) {
            uint32_t h0, m0, h1, m1;
            split2(va[j].x, va[j].y, h0, m0);
            split2(va[j].z, va[j].w, h1, m1);
            uint32_t off = (uint32_t)(arow[j] * PITCH + ac4[j] * 8);
            sts64(da + off, h0, h1);
            sts64(da + ATILE + off, m0, m1);
        }
#pragma unroll
        for (int j = 0; j < 2; j++) {
            uint32_t h0, m0, h1, m1;
            split2(vb[j].x, vb[j].y, h0, m0);
            split2(vb[j].z, vb[j].w, h1, m1);
            uint32_t off = (uint32_t)(brow[j] * PITCH + bc4[j] * 8);
            sts64(db + off, h0, h1);
            sts64(db + BTILE + off, m0, m1);
        }
    }
    __syncthreads();
    // stage 1 into registers
#pragma unroll
    for (int j = 0; j < 4; j++)
        va[j] = *(const float4*)(A + (size_t)(row0 + arow[j]) * H_DIM + KC + ac4[j] * 4);
#pragma unroll
    for (int j = 0; j < 2; j++)
        vb[j] = *(const float4*)(W + (size_t)brow[j] * H_DIM + KC + bc4[j] * 4);

    const uint32_t a_off = (uint32_t)((wid * 16 + (lane & 15)) * PITCH + (lane >> 4) * 16);
    const uint32_t b_off = (uint32_t)((((lane & 7) + ((lane >> 4) & 1) * 8)) * PITCH
                                      + ((lane >> 3) & 1) * 16);

    float acc[32];
#pragma unroll
    for (int i = 0; i < 32; i++) acc[i] = 0.0f;

    for (int i = 0; i < NSTG; i++) {
        // producer: split regs (stage i+1) -> other buffer, then LDG stage i+2
        if (i + 1 < NSTG) {
            const uint32_t da = sbase + (uint32_t)((i + 1) & 1) * STG_B;
            const uint32_t db = da + 2 * ATILE;
#pragma unroll
            for (int j = 0; j < 4; j++) {
                uint32_t h0, m0, h1, m1;
                split2(va[j].x, va[j].y, h0, m0);
                split2(va[j].z, va[j].w, h1, m1);
                uint32_t off = (uint32_t)(arow[j] * PITCH + ac4[j] * 8);
                sts64(da + off, h0, h1);
                sts64(da + ATILE + off, m0, m1);
            }
#pragma unroll
            for (int j = 0; j < 2; j++) {
                uint32_t h0, m0, h1, m1;
                split2(vb[j].x, vb[j].y, h0, m0);
                split2(vb[j].z, vb[j].w, h1, m1);
                uint32_t off = (uint32_t)(brow[j] * PITCH + bc4[j] * 8);
                sts64(db + off, h0, h1);
                sts64(db + BTILE + off, m0, m1);
            }
            if (i + 2 < NSTG) {
                const int kt = (i + 2) * KC;
#pragma unroll
                for (int j = 0; j < 4; j++)
                    va[j] = *(const float4*)(A + (size_t)(row0 + arow[j]) * H_DIM + kt + ac4[j] * 4);
#pragma unroll
                for (int j = 0; j < 2; j++)
                    vb[j] = *(const float4*)(W + (size_t)brow[j] * H_DIM + kt + bc4[j] * 4);
            }
        }

        // consumer: LDSM + MMA on current buffer (disjoint from writes above)
        const uint32_t sa = sbase + (uint32_t)(i & 1) * STG_B;
        const uint32_t sb = sa + 2 * ATILE;
#pragma unroll
        for (int ks = 0; ks < 2; ks++) {
            uint32_t aF[2][4], bF[2][16];
#pragma unroll
            for (int L = 0; L < 2; L++)
                LDSM_X4(aF[L][0], aF[L][1], aF[L][2], aF[L][3],
                        sa + L * ATILE + a_off + ks * 32);
#pragma unroll
            for (int L = 0; L < 2; L++)
#pragma unroll
                for (int np = 0; np < 4; np++)
                    LDSM_X4(bF[L][np * 4 + 0], bF[L][np * 4 + 1],
                            bF[L][np * 4 + 2], bF[L][np * 4 + 3],
                            sb + L * BTILE + (uint32_t)(np * 16 * PITCH) + b_off + ks * 32);
            // terms: hh, hm, mh (mm dropped, ~2^-22 rel)
#pragma unroll
            for (int nt = 0; nt < 8; nt++) {
                MMA16816(acc + nt * 4, aF[0], bF[0] + nt * 2);
                MMA16816(acc + nt * 4, aF[0], bF[1] + nt * 2);
                MMA16816(acc + nt * 4, aF[1], bF[0] + nt * 2);
            }
        }
        __syncthreads();   // single barrier: handoff of the buffer just written
    }

    // ---- fused epilogue ----
    float* fsm = (float*)dynsm;                 // [128][68]
    int*   si1 = (int*)(fsm + 128 * 68);
    float* sp1 = (float*)(si1 + 128);
    int*   si2 = (int*)(sp1 + 128);
    float* sp2 = (float*)(si2 + 128);

    {
        const int mrow = wid * 16 + (lane >> 2);
        const int ncol = (lane & 3) * 2;
#pragma unroll
        for (int nt = 0; nt < 8; nt++) {
            *(float2*)&fsm[mrow * 68 + nt * 8 + ncol] =
                make_float2(acc[nt * 4 + 0], acc[nt * 4 + 1]);
            *(float2*)&fsm[(mrow + 8) * 68 + nt * 8 + ncol] =
                make_float2(acc[nt * 4 + 2], acc[nt * 4 + 3]);
        }
    }
    __syncthreads();

    if (tid < 128) {
        float lg[64];
#pragma unroll
        for (int c = 0; c < 64; c++) lg[c] = fsm[tid * 68 + c];
        float mx = lg[0];
#pragma unroll
        for (int c = 1; c < 64; c++) mx = fmaxf(mx, lg[c]);
        float se = 0.0f;
#pragma unroll
        for (int c = 0; c < 64; c++) se += expf(lg[c] - mx);
        float v1 = -INFINITY; int i1 = 0;
#pragma unroll
        for (int c = 0; c < 64; c++)
            if (lg[c] > v1) { v1 = lg[c]; i1 = c; }
        float v2 = -INFINITY; int i2 = 0;
#pragma unroll
        for (int c = 0; c < 64; c++)
            if (c != i1 && lg[c] > v2) { v2 = lg[c]; i2 = c; }

        const float p1 = expf(v1 - mx) / se;
        const float p2 = expf(v2 - mx) / se;
        const float inv = 1.0f / (p1 + p2);
        const int t = row0 + tid;
        out[W_OFF + (size_t)t * 2 + 0] = p1 * inv;
        out[W_OFF + (size_t)t * 2 + 1] = p2 * inv;
        out[I_OFF + (size_t)t * 2 + 0] = (float)i1;
        out[I_OFF + (size_t)t * 2 + 1] = (float)i2;
        si1[tid] = i1; sp1[tid] = p1;
        si2[tid] = i2; sp2[tid] = p2;
    }
    __syncthreads();

#pragma unroll
    for (int j = 0; j < 8; j++) {           // coalesced logits store
        int u = j * 256 + tid, r = u >> 4, c4 = (u & 15) * 4;
        float4 v = *(float4*)&fsm[r * 68 + c4];
        *(float4*)&out[L_OFF + (size_t)(row0 + r) * 64 + c4] = v;
    }

    if (tid < E_DIM) {                       // deterministic per-block partials
        float s1 = 0.0f, s2 = 0.0f, cc = 0.0f;
        for (int r = 0; r < 128; r++) {
            float v = fsm[r * 68 + tid];
            s1 += v;
            s2 = fmaf(v, v, s2);
            if (si1[r] == tid) cc += sp1[r];
            if (si2[r] == tid) cc += sp2[r];
        }
        const int b = blockIdx.x;
        g_partials[(b * 3 + 0) * E_DIM + tid] = s1;
        g_partials[(b * 3 + 1) * E_DIM + tid] = s2;
        g_partials[(b * 3 + 2) * E_DIM + tid] = cc;
    }

    // ---- fused finalize: last block to finish does the scalar losses ----
    __syncthreads();
    __threadfence();
    __shared__ int s_last;
    if (tid == 0) s_last = (atomicAdd(&g_done, 1) == NBLK - 1) ? 1 : 0;
    __syncthreads();
    if (!s_last) return;
    __threadfence();

    // 256 threads: 4 groups x 32 blocks each, fixed-order combine
    float* red = (float*)dynsm;              // [4][3][64] — fsm no longer needed
    {
        const int g = tid >> 6, e = tid & 63;
        float s1 = 0.0f, s2 = 0.0f, c = 0.0f;
        for (int b = g * 32; b < g * 32 + 32; b++) {
            s1 += g_partials[(b * 3 + 0) * E_DIM + e];
            s2 += g_partials[(b * 3 + 1) * E_DIM + e];
            c  += g_partials[(b * 3 + 2) * E_DIM + e];
        }
        red[(g * 3 + 0) * 64 + e] = s1;
        red[(g * 3 + 1) * 64 + e] = s2;
        red[(g * 3 + 2) * 64 + e] = c;
    }
    __syncthreads();

    float* sv = red + 12 * 64;
    float* sf = sv + 64;
    if (tid < 64) {
        float s1 = 0.0f, s2 = 0.0f, c = 0.0f;
#pragma unroll
        for (int g = 0; g < 4; g++) {
            s1 += red[(g * 3 + 0) * 64 + tid];
            s2 += red[(g * 3 + 1) * 64 + tid];
            c  += red[(g * 3 + 2) * 64 + tid];
        }
        const float invT = 1.0f / (float)T_TOK;
        const float mean = s1 * invT;
        sv[tid] = s2 * invT - mean * mean;
        sf[tid] = c * invT;
    }
    __syncthreads();
    if (tid == 0) {
        float vsum = 0.0f, fsum = 0.0f;
        for (int i = 0; i < E_DIM; i++) { vsum += sv[i]; fsum += sf[i]; }
        out[Z_OFF] = (vsum / (float)E_DIM) * 0.001f;
        const float meanf = fsum / (float)E_DIM;
        float a2 = 0.0f;
        for (int i = 0; i < E_DIM; i++) {
            const float d = sf[i] - meanf;
            a2 = fmaf(d, d, a2);
        }
        out[LB_OFF] = (sqrtf(a2 / (float)(E_DIM - 1)) / (meanf + 1e-8f)) * 0.01f;
        g_done = 0;                           // reset for next graph replay
    }
}

extern "C" void kernel_launch(void* const* d_in, const int* in_sizes, int n_in,
                              void* d_out, int out_size)
{
    const float* hs = (const float*)d_in[0];
    const float* W  = (const float*)d_in[1];
    if (n_in >= 2 && in_sizes[0] < in_sizes[1]) {
        const float* t = hs; hs = W; W = t;
    }
    float* out = (float*)d_out;
    cudaFuncSetAttribute(fused_router_kernel,
                         cudaFuncAttributeMaxDynamicSharedMemorySize, DYN_B);
    fused_router_kernel<<<NBLK, 256, DYN_B>>>(hs, W, out);
}

// round 6
// speedup vs baseline: 2.2013x; 1.0268x over previous
#include <cuda_runtime.h>
#include <cuda_fp16.h>
#include <math.h>
#include <stdint.h>

#define T_TOK   16384
#define H_DIM   2048
#define E_DIM   64
#define BM      64
#define KC      32
#define NSTG    (H_DIM / KC)            // 64
#define NBLK    (T_TOK / BM)            // 256

#define W_OFF   0
#define I_OFF   32768
#define L_OFF   65536
#define Z_OFF   1114112
#define LB_OFF  1114113

#define PITCH   80                      // 64B (32 fp16) + 16B pad per k-row
#define ATILE   (BM * PITCH)            // 5120 B per A limb
#define BTILE   (E_DIM * PITCH)         // 5120 B per B limb
#define STG_B   (2 * ATILE + 2 * BTILE) // 20480 B per stage
#define DYN_B   (2 * STG_B)             // 40960 -> 2 CTAs/SM

__device__ float g_partials[NBLK * 3 * E_DIM];
__device__ int   g_done = 0;

__device__ __forceinline__ uint32_t smem_u32(const void* p) {
    uint32_t a;
    asm("{ .reg .u64 t; cvta.to.shared.u64 t, %1; cvt.u32.u64 %0, t; }" : "=r"(a) : "l"(p));
    return a;
}
__device__ __forceinline__ void sts64(uint32_t a, uint32_t x, uint32_t y) {
    asm volatile("st.shared.v2.b32 [%0], {%1, %2};" :: "r"(a), "r"(x), "r"(y));
}
#define LDSM_X4(r0, r1, r2, r3, addr)                                         \
    asm volatile("ldmatrix.sync.aligned.m8n8.x4.shared.b16 {%0,%1,%2,%3}, [%4];" \
                 : "=r"(r0), "=r"(r1), "=r"(r2), "=r"(r3) : "r"(addr))
#define MMA16816(d, a, b)                                                     \
    asm volatile("mma.sync.aligned.m16n8k16.row.col.f32.f16.f16.f32 "         \
                 "{%0,%1,%2,%3}, {%4,%5,%6,%7}, {%8,%9}, {%0,%1,%2,%3};"      \
                 : "+f"((d)[0]), "+f"((d)[1]), "+f"((d)[2]), "+f"((d)[3])     \
                 : "r"((a)[0]), "r"((a)[1]), "r"((a)[2]), "r"((a)[3]),        \
                   "r"((b)[0]), "r"((b)[1]))

// 2-limb fp16 split: h+m ~ x to 2^-22 rel; residual subtraction exact.
__device__ __forceinline__ void split2(float x0, float x1, uint32_t& h, uint32_t& m) {
    __half2 h2 = __floats2half2_rn(x0, x1);
    h = *reinterpret_cast<uint32_t*>(&h2);
    float2 hf = __half22float2(h2);
    __half2 m2 = __floats2half2_rn(x0 - hf.x, x1 - hf.y);
    m = *reinterpret_cast<uint32_t*>(&m2);
}

__global__ __launch_bounds__(256, 2)
void fused_router_kernel(const float* __restrict__ A, const float* __restrict__ W,
                         float* __restrict__ out)
{
    extern __shared__ __align__(16) unsigned char dynsm[];
    const uint32_t sbase = smem_u32(dynsm);

    const int tid  = threadIdx.x;
    const int wid  = tid >> 5;
    const int lane = tid & 31;
    const int row0 = blockIdx.x * BM;

    // global-load assignment: A 512 float4 -> 2/thread, B 512 float4 -> 2/thread
    int arow[2], ac4[2], brow[2], bc4[2];
#pragma unroll
    for (int j = 0; j < 2; j++) {
        int f = tid + j * 256;
        arow[j] = f >> 3; ac4[j] = f & 7;
        brow[j] = f >> 3; bc4[j] = f & 7;
    }

    float4 va[2], vb[2];

    // ---- prologue: stage 0 -> buf0 ----
#pragma unroll
    for (int j = 0; j < 2; j++) {
        va[j] = *(const float4*)(A + (size_t)(row0 + arow[j]) * H_DIM + ac4[j] * 4);
        vb[j] = *(const float4*)(W + (size_t)brow[j] * H_DIM + bc4[j] * 4);
    }
    {
        const uint32_t da = sbase, db = sbase + 2 * ATILE;
#pragma unroll
        for (int j = 0; j < 2; j++) {
            uint32_t h0, m0, h1, m1;
            split2(va[j].x, va[j].y, h0, m0);
            split2(va[j].z, va[j].w, h1, m1);
            uint32_t off = (uint32_t)(arow[j] * PITCH + ac4[j] * 8);
            sts64(da + off, h0, h1);
            sts64(da + ATILE + off, m0, m1);
            split2(vb[j].x, vb[j].y, h0, m0);
            split2(vb[j].z, vb[j].w, h1, m1);
            off = (uint32_t)(brow[j] * PITCH + bc4[j] * 8);
            sts64(db + off, h0, h1);
            sts64(db + BTILE + off, m0, m1);
        }
    }
    __syncthreads();
#pragma unroll
    for (int j = 0; j < 2; j++) {   // stage 1 into registers
        va[j] = *(const float4*)(A + (size_t)(row0 + arow[j]) * H_DIM + KC + ac4[j] * 4);
        vb[j] = *(const float4*)(W + (size_t)brow[j] * H_DIM + KC + bc4[j] * 4);
    }

    // warp tile: mstrip = wid&3 (16 rows), nhalf = wid>>2 (32 experts)
    const int mstrip = wid & 3, nhalf = wid >> 2;
    const uint32_t a_off = (uint32_t)((mstrip * 16 + (lane & 15)) * PITCH + (lane >> 4) * 16);
    const uint32_t b_off = (uint32_t)((nhalf * 32 + (lane & 7) + ((lane >> 4) & 1) * 8) * PITCH
                                      + ((lane >> 3) & 1) * 16);

    float acc[16];
#pragma unroll
    for (int i = 0; i < 16; i++) acc[i] = 0.0f;

    for (int i = 0; i < NSTG; i++) {
        // producer: split regs (stage i+1) -> other buffer, then LDG stage i+2
        if (i + 1 < NSTG) {
            const uint32_t da = sbase + (uint32_t)((i + 1) & 1) * STG_B;
            const uint32_t db = da + 2 * ATILE;
#pragma unroll
            for (int j = 0; j < 2; j++) {
                uint32_t h0, m0, h1, m1;
                split2(va[j].x, va[j].y, h0, m0);
                split2(va[j].z, va[j].w, h1, m1);
                uint32_t off = (uint32_t)(arow[j] * PITCH + ac4[j] * 8);
                sts64(da + off, h0, h1);
                sts64(da + ATILE + off, m0, m1);
                split2(vb[j].x, vb[j].y, h0, m0);
                split2(vb[j].z, vb[j].w, h1, m1);
                off = (uint32_t)(brow[j] * PITCH + bc4[j] * 8);
                sts64(db + off, h0, h1);
                sts64(db + BTILE + off, m0, m1);
            }
            if (i + 2 < NSTG) {
                const int kt = (i + 2) * KC;
#pragma unroll
                for (int j = 0; j < 2; j++) {
                    va[j] = *(const float4*)(A + (size_t)(row0 + arow[j]) * H_DIM + kt + ac4[j] * 4);
                    vb[j] = *(const float4*)(W + (size_t)brow[j] * H_DIM + kt + bc4[j] * 4);
                }
            }
        }

        // consumer: LDSM + MMA on current buffer
        const uint32_t sa = sbase + (uint32_t)(i & 1) * STG_B;
        const uint32_t sb = sa + 2 * ATILE;
#pragma unroll
        for (int ks = 0; ks < 2; ks++) {
            uint32_t aF[2][4], bF[2][8];
#pragma unroll
            for (int L = 0; L < 2; L++)
                LDSM_X4(aF[L][0], aF[L][1], aF[L][2], aF[L][3],
                        sa + L * ATILE + a_off + ks * 32);
#pragma unroll
            for (int L = 0; L < 2; L++)
#pragma unroll
                for (int np = 0; np < 2; np++)
                    LDSM_X4(bF[L][np * 4 + 0], bF[L][np * 4 + 1],
                            bF[L][np * 4 + 2], bF[L][np * 4 + 3],
                            sb + L * BTILE + (uint32_t)(np * 16 * PITCH) + b_off + ks * 32);
            // terms: hh, hm, mh (mm dropped, ~2^-22 rel)
#pragma unroll
            for (int nt = 0; nt < 4; nt++) {
                MMA16816(acc + nt * 4, aF[0], bF[0] + nt * 2);
                MMA16816(acc + nt * 4, aF[0], bF[1] + nt * 2);
                MMA16816(acc + nt * 4, aF[1], bF[0] + nt * 2);
            }
        }
        __syncthreads();
    }

    // ---- fused epilogue ----
    float* fsm = (float*)dynsm;                 // [64][68]
    int*   si1 = (int*)(fsm + 64 * 68);
    float* sp1 = (float*)(si1 + 64);
    int*   si2 = (int*)(sp1 + 64);
    float* sp2 = (float*)(si2 + 64);

    {
        const int mrow = mstrip * 16 + (lane >> 2);
        const int ncol = nhalf * 32 + (lane & 3) * 2;
#pragma unroll
        for (int nt = 0; nt < 4; nt++) {
            *(float2*)&fsm[mrow * 68 + ncol + nt * 8] =
                make_float2(acc[nt * 4 + 0], acc[nt * 4 + 1]);
            *(float2*)&fsm[(mrow + 8) * 68 + ncol + nt * 8] =
                make_float2(acc[nt * 4 + 2], acc[nt * 4 + 3]);
        }
    }
    __syncthreads();

    if (tid < BM) {
        float lg[64];
#pragma unroll
        for (int c = 0; c < 64; c++) lg[c] = fsm[tid * 68 + c];
        float mx = lg[0];
#pragma unroll
        for (int c = 1; c < 64; c++) mx = fmaxf(mx, lg[c]);
        float se = 0.0f;
#pragma unroll
        for (int c = 0; c < 64; c++) se += expf(lg[c] - mx);
        float v1 = -INFINITY; int i1 = 0;
#pragma unroll
        for (int c = 0; c < 64; c++)
            if (lg[c] > v1) { v1 = lg[c]; i1 = c; }
        float v2 = -INFINITY; int i2 = 0;
#pragma unroll
        for (int c = 0; c < 64; c++)
            if (c != i1 && lg[c] > v2) { v2 = lg[c]; i2 = c; }

        const float p1 = expf(v1 - mx) / se;
        const float p2 = expf(v2 - mx) / se;
        const float inv = 1.0f / (p1 + p2);
        const int t = row0 + tid;
        out[W_OFF + (size_t)t * 2 + 0] = p1 * inv;
        out[W_OFF + (size_t)t * 2 + 1] = p2 * inv;
        out[I_OFF + (size_t)t * 2 + 0] = (float)i1;
        out[I_OFF + (size_t)t * 2 + 1] = (float)i2;
        si1[tid] = i1; sp1[tid] = p1;
        si2[tid] = i2; sp2[tid] = p2;
    }
    __syncthreads();

#pragma unroll
    for (int j = 0; j < 4; j++) {           // coalesced logits store
        int u = j * 256 + tid, r = u >> 4, c4 = (u & 15) * 4;
        float4 v = *(float4*)&fsm[r * 68 + c4];
        *(float4*)&out[L_OFF + (size_t)(row0 + r) * 64 + c4] = v;
    }

    if (tid < E_DIM) {                       // deterministic per-block partials
        float s1 = 0.0f, s2 = 0.0f, cc = 0.0f;
        for (int r = 0; r < BM; r++) {
            float v = fsm[r * 68 + tid];
            s1 += v;
            s2 = fmaf(v, v, s2);
            if (si1[r] == tid) cc += sp1[r];
            if (si2[r] == tid) cc += sp2[r];
        }
        const int b = blockIdx.x;
        g_partials[(b * 3 + 0) * E_DIM + tid] = s1;
        g_partials[(b * 3 + 1) * E_DIM + tid] = s2;
        g_partials[(b * 3 + 2) * E_DIM + tid] = cc;
    }

    // ---- fused finalize: last block computes scalar losses ----
    __syncthreads();
    __threadfence();
    __shared__ int s_last;
    if (tid == 0) s_last = (atomicAdd(&g_done, 1) == NBLK - 1) ? 1 : 0;
    __syncthreads();
    if (!s_last) return;
    __threadfence();

    float* red = (float*)dynsm;              // [4][3][64]
    {
        const int g = tid >> 6, e = tid & 63;
        float s1 = 0.0f, s2 = 0.0f, c = 0.0f;
        for (int b = g * 64; b < g * 64 + 64; b++) {
            s1 += g_partials[(b * 3 + 0) * E_DIM + e];
            s2 += g_partials[(b * 3 + 1) * E_DIM + e];
            c  += g_partials[(b * 3 + 2) * E_DIM + e];
        }
        red[(g * 3 + 0) * 64 + e] = s1;
        red[(g * 3 + 1) * 64 + e] = s2;
        red[(g * 3 + 2) * 64 + e] = c;
    }
    __syncthreads();

    float* sv = red + 12 * 64;
    float* sf = sv + 64;
    if (tid < 64) {
        float s1 = 0.0f, s2 = 0.0f, c = 0.0f;
#pragma unroll
        for (int g = 0; g < 4; g++) {
            s1 += red[(g * 3 + 0) * 64 + tid];
            s2 += red[(g * 3 + 1) * 64 + tid];
            c  += red[(g * 3 + 2) * 64 + tid];
        }
        const float invT = 1.0f / (float)T_TOK;
        const float mean = s1 * invT;
        sv[tid] = s2 * invT - mean * mean;
        sf[tid] = c * invT;
    }
    __syncthreads();
    if (tid == 0) {
        float vsum = 0.0f, fsum = 0.0f;
        for (int i = 0; i < E_DIM; i++) { vsum += sv[i]; fsum += sf[i]; }
        out[Z_OFF] = (vsum / (float)E_DIM) * 0.001f;
        const float meanf = fsum / (float)E_DIM;
        float a2 = 0.0f;
        for (int i = 0; i < E_DIM; i++) {
            const float d = sf[i] - meanf;
            a2 = fmaf(d, d, a2);
        }
        out[LB_OFF] = (sqrtf(a2 / (float)(E_DIM - 1)) / (meanf + 1e-8f)) * 0.01f;
        g_done = 0;
    }
}

extern "C" void kernel_launch(void* const* d_in, const int* in_sizes, int n_in,
                              void* d_out, int out_size)
{
    const float* hs = (const float*)d_in[0];
    const float* W  = (const float*)d_in[1];
    if (n_in >= 2 && in_sizes[0] < in_sizes[1]) {
        const float* t = hs; hs = W; W = t;
    }
    float* out = (float*)d_out;
    cudaFuncSetAttribute(fused_router_kernel,
                         cudaFuncAttributeMaxDynamicSharedMemorySize, DYN_B);
    fused_router_kernel<<<NBLK, 256, DYN_B>>>(hs, W, out);
}